// round 5
// baseline (speedup 1.0000x reference)
#include <cuda_runtime.h>
#include <math.h>

// Shapes:
//   x      [32,64,64,512] f32 NHWC
//   base_w [3,3,512,256]  HWIO
//   base_b [256]
//   cls_w  [1,1,256,9], cls_b [9]
//   reg_w  [1,1,256,36], reg_b [36]
//   out    [32,64,64,45]

#define NPIX (32 * 64 * 64)

__device__ float g_feat[(size_t)NPIX * 256];

// ---- packed f32x2 helpers (Blackwell FFMA2 path; ptxas won't auto-fuse) ----
__device__ __forceinline__ void fma2(unsigned long long& d,
                                     unsigned long long a,
                                     unsigned long long b)
{
    asm("fma.rn.f32x2 %0, %1, %2, %0;" : "+l"(d) : "l"(a), "l"(b));
}
__device__ __forceinline__ unsigned long long dup2(float v)
{
    unsigned long long r;
    unsigned u = __float_as_uint(v);
    asm("mov.b64 %0, {%1, %1};" : "=l"(r) : "r"(u));
    return r;
}

// ---------------------------------------------------------------------------
// Stage 1: 3x3 conv + bias + ReLU, implicit GEMM.
//   M = NPIX, N = 256, K = 9*512. BM=128, BN=128, BK=8, 256 thr, 8x8/thread.
//   Double-buffered SMEM (1 bar/k-tile) + packed FFMA2 inner product.
// ---------------------------------------------------------------------------
__global__ void __launch_bounds__(256, 2)
conv3x3_relu_kernel(const float* __restrict__ x,
                    const float* __restrict__ wbase,
                    const float* __restrict__ bbase)
{
    __shared__ float As[2][8][132];   // transposed [k][m], pad 132 (conflict-free)
    __shared__ float Bs[2][8][128];

    const int tid  = threadIdx.x;
    const int nblk = blockIdx.x;      // 0..1
    const int mblk = blockIdx.y;      // 0..1023

    // global-load mapping
    const int arow = tid >> 1;        // 0..127 pixel
    const int acol = tid & 1;         // k-quad
    const int brow = tid >> 5;        // 0..7 k row
    const int bcol = tid & 31;        // n-quad

    const int p  = mblk * 128 + arow;
    const int pb = p >> 12;
    const int ph = (p >> 6) & 63;
    const int pw = p & 63;

    // compute mapping: 16x16 threads, 8x8 outputs
    const int tr = tid >> 4;
    const int tc = tid & 15;
    const int m0 = tr * 8;
    const int n0 = tc * 8;

    // packed accumulators: acc2[i][j2] = {acc[i][2j2], acc[i][2j2+1]}
    unsigned long long acc2[8][4];
#pragma unroll
    for (int i = 0; i < 8; i++)
#pragma unroll
        for (int j = 0; j < 4; j++) acc2[i][j] = 0ull;

    int buf = 0;

#pragma unroll 1
    for (int pos = 0; pos < 9; pos++) {
        const int ky  = pos / 3;
        const int kx  = pos - ky * 3;
        const int hin = ph + ky - 1;
        const int win = pw + kx - 1;
        const bool valid = ((unsigned)hin < 64u) && ((unsigned)win < 64u);
        const float* aptr = x + ((((pb * 64 + hin) * 64) + win) * 512 + acol * 4);
        const float* bptr = wbase + (pos * 512 * 256 + brow * 256 + nblk * 128 + bcol * 4);

        // prologue: stage cc=0 into the idle buffer
        {
            float4 av = make_float4(0.f, 0.f, 0.f, 0.f);
            if (valid) av = *(const float4*)(aptr);
            const float4 bv = *(const float4*)(bptr);
            const int nb = buf ^ 1;
            As[nb][acol * 4 + 0][arow] = av.x;
            As[nb][acol * 4 + 1][arow] = av.y;
            As[nb][acol * 4 + 2][arow] = av.z;
            As[nb][acol * 4 + 3][arow] = av.w;
            *(float4*)(&Bs[nb][brow][bcol * 4]) = bv;
            __syncthreads();
            buf = nb;
        }

#pragma unroll 1
        for (int cc = 0; cc < 64; cc++) {
            float4 av2, bv2;
            if (cc < 63) {
                av2 = make_float4(0.f, 0.f, 0.f, 0.f);
                if (valid) av2 = *(const float4*)(aptr + (cc + 1) * 8);
                bv2 = *(const float4*)(bptr + (cc + 1) * 2048);
            }

#pragma unroll
            for (int k = 0; k < 8; k++) {
                const float* asrc = &As[buf][k][m0];
                const float4 a0 = *(const float4*)(asrc);
                const float4 a1 = *(const float4*)(asrc + 4);
                const unsigned long long* bp =
                    (const unsigned long long*)(&Bs[buf][k][n0]);
                const unsigned long long b0 = bp[0], b1 = bp[1],
                                         b2 = bp[2], b3 = bp[3];

                unsigned long long ad;
                ad = dup2(a0.x);
                fma2(acc2[0][0], ad, b0); fma2(acc2[0][1], ad, b1);
                fma2(acc2[0][2], ad, b2); fma2(acc2[0][3], ad, b3);
                ad = dup2(a0.y);
                fma2(acc2[1][0], ad, b0); fma2(acc2[1][1], ad, b1);
                fma2(acc2[1][2], ad, b2); fma2(acc2[1][3], ad, b3);
                ad = dup2(a0.z);
                fma2(acc2[2][0], ad, b0); fma2(acc2[2][1], ad, b1);
                fma2(acc2[2][2], ad, b2); fma2(acc2[2][3], ad, b3);
                ad = dup2(a0.w);
                fma2(acc2[3][0], ad, b0); fma2(acc2[3][1], ad, b1);
                fma2(acc2[3][2], ad, b2); fma2(acc2[3][3], ad, b3);
                ad = dup2(a1.x);
                fma2(acc2[4][0], ad, b0); fma2(acc2[4][1], ad, b1);
                fma2(acc2[4][2], ad, b2); fma2(acc2[4][3], ad, b3);
                ad = dup2(a1.y);
                fma2(acc2[5][0], ad, b0); fma2(acc2[5][1], ad, b1);
                fma2(acc2[5][2], ad, b2); fma2(acc2[5][3], ad, b3);
                ad = dup2(a1.z);
                fma2(acc2[6][0], ad, b0); fma2(acc2[6][1], ad, b1);
                fma2(acc2[6][2], ad, b2); fma2(acc2[6][3], ad, b3);
                ad = dup2(a1.w);
                fma2(acc2[7][0], ad, b0); fma2(acc2[7][1], ad, b1);
                fma2(acc2[7][2], ad, b2); fma2(acc2[7][3], ad, b3);
            }

            if (cc < 63) {
                const int nb = buf ^ 1;
                As[nb][acol * 4 + 0][arow] = av2.x;
                As[nb][acol * 4 + 1][arow] = av2.y;
                As[nb][acol * 4 + 2][arow] = av2.z;
                As[nb][acol * 4 + 3][arow] = av2.w;
                *(float4*)(&Bs[nb][brow][bcol * 4]) = bv2;
                __syncthreads();
                buf = nb;
            }
        }
    }

    // epilogue: bias + ReLU, store feat tile
    float bias[8];
#pragma unroll
    for (int j = 0; j < 8; j++) bias[j] = bbase[nblk * 128 + n0 + j];

#pragma unroll
    for (int i = 0; i < 8; i++) {
        const int pm = mblk * 128 + m0 + i;
        float* dst = g_feat + (size_t)pm * 256 + nblk * 128 + n0;
        float v[8];
#pragma unroll
        for (int j2 = 0; j2 < 4; j2++) {
            v[2 * j2 + 0] = __uint_as_float((unsigned)(acc2[i][j2] & 0xffffffffull));
            v[2 * j2 + 1] = __uint_as_float((unsigned)(acc2[i][j2] >> 32));
        }
        float4 v0, v1;
        v0.x = fmaxf(v[0] + bias[0], 0.f);
        v0.y = fmaxf(v[1] + bias[1], 0.f);
        v0.z = fmaxf(v[2] + bias[2], 0.f);
        v0.w = fmaxf(v[3] + bias[3], 0.f);
        v1.x = fmaxf(v[4] + bias[4], 0.f);
        v1.y = fmaxf(v[5] + bias[5], 0.f);
        v1.z = fmaxf(v[6] + bias[6], 0.f);
        v1.w = fmaxf(v[7] + bias[7], 0.f);
        *(float4*)(dst)     = v0;
        *(float4*)(dst + 4) = v1;
    }
}

// ---------------------------------------------------------------------------
// Stage 2: fused 1x1 heads + sigmoid + anchor filter + concat store.
// ---------------------------------------------------------------------------
__global__ void __launch_bounds__(256)
rpn_head_kernel(const float* __restrict__ cls_w,
                const float* __restrict__ cls_b,
                const float* __restrict__ reg_w,
                const float* __restrict__ reg_b,
                float* __restrict__ out)
{
    __shared__ float wsm[256 * 45];
    for (int idx = threadIdx.x; idx < 256 * 45; idx += 256) {
        const int c = idx / 45;
        const int j = idx - c * 45;
        wsm[idx] = (j < 36) ? reg_w[c * 36 + j] : cls_w[c * 9 + (j - 36)];
    }
    __syncthreads();

    const int p = blockIdx.x * 256 + threadIdx.x;
    const float* f = g_feat + (size_t)p * 256;

    float acc[45];
#pragma unroll
    for (int j = 0; j < 45; j++) acc[j] = 0.0f;

#pragma unroll 1
    for (int c4 = 0; c4 < 64; c4++) {
        const float4 fv = *(const float4*)(f + c4 * 4);
        const float* w0 = &wsm[(c4 * 4 + 0) * 45];
        const float* w1 = &wsm[(c4 * 4 + 1) * 45];
        const float* w2 = &wsm[(c4 * 4 + 2) * 45];
        const float* w3 = &wsm[(c4 * 4 + 3) * 45];
#pragma unroll
        for (int j = 0; j < 45; j++) {
            float t = acc[j];
            t = fmaf(fv.x, w0[j], t);
            t = fmaf(fv.y, w1[j], t);
            t = fmaf(fv.z, w2[j], t);
            t = fmaf(fv.w, w3[j], t);
            acc[j] = t;
        }
    }

#pragma unroll
    for (int j = 0; j < 36; j++) acc[j] += reg_b[j];
#pragma unroll
    for (int a = 0; a < 9; a++) {
        const float z = acc[36 + a] + cls_b[a];
        acc[36 + a] = 1.0f / (1.0f + expf(-z));
    }

    float* o = out + (size_t)p * 45;
#pragma unroll
    for (int a = 0; a < 9; a++) {
        const bool keep = (acc[36 + a] > 0.7f) &&
                          (acc[4 * a + 2] > 10.0f) &&
                          (acc[4 * a + 3] > 10.0f);
        const float m = keep ? 1.0f : 0.0f;
        o[4 * a + 0] = acc[4 * a + 0] * m;
        o[4 * a + 1] = acc[4 * a + 1] * m;
        o[4 * a + 2] = acc[4 * a + 2] * m;
        o[4 * a + 3] = acc[4 * a + 3] * m;
        o[36 + a]    = acc[36 + a];
    }
}

extern "C" void kernel_launch(void* const* d_in, const int* in_sizes, int n_in,
                              void* d_out, int out_size)
{
    const float* x      = (const float*)d_in[0];
    const float* base_w = (const float*)d_in[1];
    const float* base_b = (const float*)d_in[2];
    const float* cls_w  = (const float*)d_in[3];
    const float* cls_b  = (const float*)d_in[4];
    const float* reg_w  = (const float*)d_in[5];
    const float* reg_b  = (const float*)d_in[6];
    float* out = (float*)d_out;

    dim3 g1(2, 1024, 1);
    conv3x3_relu_kernel<<<g1, 256>>>(x, base_w, base_b);
    rpn_head_kernel<<<512, 256>>>(cls_w, cls_b, reg_w, reg_b, out);
}

// round 6
// speedup vs baseline: 1.0556x; 1.0556x over previous
#include <cuda_runtime.h>
#include <math.h>

// Shapes:
//   x      [32,64,64,512] f32 NHWC
//   base_w [3,3,512,256]  HWIO
//   base_b [256]
//   cls_w  [1,1,256,9], cls_b [9]
//   reg_w  [1,1,256,36], reg_b [36]
//   out    [32,64,64,45]

#define NPIX (32 * 64 * 64)

__device__ float g_feat[(size_t)NPIX * 256];

// ---- packed f32x2 helpers (Blackwell FFMA2 path; ptxas won't auto-fuse) ----
__device__ __forceinline__ void fma2(unsigned long long& d,
                                     unsigned long long a,
                                     unsigned long long b)
{
    asm("fma.rn.f32x2 %0, %1, %2, %0;" : "+l"(d) : "l"(a), "l"(b));
}
__device__ __forceinline__ unsigned long long dup2(float v)
{
    unsigned long long r;
    unsigned u = __float_as_uint(v);
    asm("mov.b64 %0, {%1, %1};" : "=l"(r) : "r"(u));
    return r;
}

// ---------------------------------------------------------------------------
// Stage 1: 3x3 conv + bias + ReLU, implicit GEMM.
//   M = NPIX, N = 256, K = 9*512. BM=128, BN=128, BK=8, 256 thr, 8x8/thread.
//   Double-buffered SMEM (1 bar/k-tile) + packed FFMA2 inner product.
// ---------------------------------------------------------------------------
__global__ void __launch_bounds__(256, 2)
conv3x3_relu_kernel(const float* __restrict__ x,
                    const float* __restrict__ wbase,
                    const float* __restrict__ bbase)
{
    __shared__ float As[2][8][132];   // transposed [k][m], pad 132 (conflict-free)
    __shared__ float Bs[2][8][128];

    const int tid  = threadIdx.x;
    const int nblk = blockIdx.x;      // 0..1
    const int mblk = blockIdx.y;      // 0..1023

    // global-load mapping
    const int arow = tid >> 1;        // 0..127 pixel
    const int acol = tid & 1;         // k-quad
    const int brow = tid >> 5;        // 0..7 k row
    const int bcol = tid & 31;        // n-quad

    const int p  = mblk * 128 + arow;
    const int pb = p >> 12;
    const int ph = (p >> 6) & 63;
    const int pw = p & 63;

    // compute mapping: 16x16 threads, 8x8 outputs
    const int tr = tid >> 4;
    const int tc = tid & 15;
    const int m0 = tr * 8;
    const int n0 = tc * 8;

    // packed accumulators: acc2[i][j2] = {acc[i][2j2], acc[i][2j2+1]}
    unsigned long long acc2[8][4];
#pragma unroll
    for (int i = 0; i < 8; i++)
#pragma unroll
        for (int j = 0; j < 4; j++) acc2[i][j] = 0ull;

    int buf = 0;

#pragma unroll 1
    for (int pos = 0; pos < 9; pos++) {
        const int ky  = pos / 3;
        const int kx  = pos - ky * 3;
        const int hin = ph + ky - 1;
        const int win = pw + kx - 1;
        const bool valid = ((unsigned)hin < 64u) && ((unsigned)win < 64u);
        const float* aptr = x + ((((pb * 64 + hin) * 64) + win) * 512 + acol * 4);
        const float* bptr = wbase + (pos * 512 * 256 + brow * 256 + nblk * 128 + bcol * 4);

        // prologue: stage cc=0 into the idle buffer
        {
            float4 av = make_float4(0.f, 0.f, 0.f, 0.f);
            if (valid) av = *(const float4*)(aptr);
            const float4 bv = *(const float4*)(bptr);
            const int nb = buf ^ 1;
            As[nb][acol * 4 + 0][arow] = av.x;
            As[nb][acol * 4 + 1][arow] = av.y;
            As[nb][acol * 4 + 2][arow] = av.z;
            As[nb][acol * 4 + 3][arow] = av.w;
            *(float4*)(&Bs[nb][brow][bcol * 4]) = bv;
            __syncthreads();
            buf = nb;
        }

#pragma unroll 1
        for (int cc = 0; cc < 64; cc++) {
            float4 av2, bv2;
            if (cc < 63) {
                av2 = make_float4(0.f, 0.f, 0.f, 0.f);
                if (valid) av2 = *(const float4*)(aptr + (cc + 1) * 8);
                bv2 = *(const float4*)(bptr + (cc + 1) * 2048);
            }

#pragma unroll
            for (int k = 0; k < 8; k++) {
                const float* asrc = &As[buf][k][m0];
                const float4 a0 = *(const float4*)(asrc);
                const float4 a1 = *(const float4*)(asrc + 4);
                const unsigned long long* bp =
                    (const unsigned long long*)(&Bs[buf][k][n0]);
                const unsigned long long b0 = bp[0], b1 = bp[1],
                                         b2 = bp[2], b3 = bp[3];

                unsigned long long ad;
                ad = dup2(a0.x);
                fma2(acc2[0][0], ad, b0); fma2(acc2[0][1], ad, b1);
                fma2(acc2[0][2], ad, b2); fma2(acc2[0][3], ad, b3);
                ad = dup2(a0.y);
                fma2(acc2[1][0], ad, b0); fma2(acc2[1][1], ad, b1);
                fma2(acc2[1][2], ad, b2); fma2(acc2[1][3], ad, b3);
                ad = dup2(a0.z);
                fma2(acc2[2][0], ad, b0); fma2(acc2[2][1], ad, b1);
                fma2(acc2[2][2], ad, b2); fma2(acc2[2][3], ad, b3);
                ad = dup2(a0.w);
                fma2(acc2[3][0], ad, b0); fma2(acc2[3][1], ad, b1);
                fma2(acc2[3][2], ad, b2); fma2(acc2[3][3], ad, b3);
                ad = dup2(a1.x);
                fma2(acc2[4][0], ad, b0); fma2(acc2[4][1], ad, b1);
                fma2(acc2[4][2], ad, b2); fma2(acc2[4][3], ad, b3);
                ad = dup2(a1.y);
                fma2(acc2[5][0], ad, b0); fma2(acc2[5][1], ad, b1);
                fma2(acc2[5][2], ad, b2); fma2(acc2[5][3], ad, b3);
                ad = dup2(a1.z);
                fma2(acc2[6][0], ad, b0); fma2(acc2[6][1], ad, b1);
                fma2(acc2[6][2], ad, b2); fma2(acc2[6][3], ad, b3);
                ad = dup2(a1.w);
                fma2(acc2[7][0], ad, b0); fma2(acc2[7][1], ad, b1);
                fma2(acc2[7][2], ad, b2); fma2(acc2[7][3], ad, b3);
            }

            if (cc < 63) {
                const int nb = buf ^ 1;
                As[nb][acol * 4 + 0][arow] = av2.x;
                As[nb][acol * 4 + 1][arow] = av2.y;
                As[nb][acol * 4 + 2][arow] = av2.z;
                As[nb][acol * 4 + 3][arow] = av2.w;
                *(float4*)(&Bs[nb][brow][bcol * 4]) = bv2;
                __syncthreads();
                buf = nb;
            }
        }
    }

    // epilogue: bias + ReLU, store feat tile
    float bias[8];
#pragma unroll
    for (int j = 0; j < 8; j++) bias[j] = bbase[nblk * 128 + n0 + j];

#pragma unroll
    for (int i = 0; i < 8; i++) {
        const int pm = mblk * 128 + m0 + i;
        float* dst = g_feat + (size_t)pm * 256 + nblk * 128 + n0;
        float v[8];
#pragma unroll
        for (int j2 = 0; j2 < 4; j2++) {
            v[2 * j2 + 0] = __uint_as_float((unsigned)(acc2[i][j2] & 0xffffffffull));
            v[2 * j2 + 1] = __uint_as_float((unsigned)(acc2[i][j2] >> 32));
        }
        float4 v0, v1;
        v0.x = fmaxf(v[0] + bias[0], 0.f);
        v0.y = fmaxf(v[1] + bias[1], 0.f);
        v0.z = fmaxf(v[2] + bias[2], 0.f);
        v0.w = fmaxf(v[3] + bias[3], 0.f);
        v1.x = fmaxf(v[4] + bias[4], 0.f);
        v1.y = fmaxf(v[5] + bias[5], 0.f);
        v1.z = fmaxf(v[6] + bias[6], 0.f);
        v1.w = fmaxf(v[7] + bias[7], 0.f);
        *(float4*)(dst)     = v0;
        *(float4*)(dst + 4) = v1;
    }
}

// ---------------------------------------------------------------------------
// Stage 2: fused 1x1 heads + sigmoid + anchor filter + concat store.
// ---------------------------------------------------------------------------
__global__ void __launch_bounds__(256)
rpn_head_kernel(const float* __restrict__ cls_w,
                const float* __restrict__ cls_b,
                const float* __restrict__ reg_w,
                const float* __restrict__ reg_b,
                float* __restrict__ out)
{
    __shared__ float wsm[256 * 45];
    for (int idx = threadIdx.x; idx < 256 * 45; idx += 256) {
        const int c = idx / 45;
        const int j = idx - c * 45;
        wsm[idx] = (j < 36) ? reg_w[c * 36 + j] : cls_w[c * 9 + (j - 36)];
    }
    __syncthreads();

    const int p = blockIdx.x * 256 + threadIdx.x;
    const float* f = g_feat + (size_t)p * 256;

    float acc[45];
#pragma unroll
    for (int j = 0; j < 45; j++) acc[j] = 0.0f;

#pragma unroll 1
    for (int c4 = 0; c4 < 64; c4++) {
        const float4 fv = *(const float4*)(f + c4 * 4);
        const float* w0 = &wsm[(c4 * 4 + 0) * 45];
        const float* w1 = &wsm[(c4 * 4 + 1) * 45];
        const float* w2 = &wsm[(c4 * 4 + 2) * 45];
        const float* w3 = &wsm[(c4 * 4 + 3) * 45];
#pragma unroll
        for (int j = 0; j < 45; j++) {
            float t = acc[j];
            t = fmaf(fv.x, w0[j], t);
            t = fmaf(fv.y, w1[j], t);
            t = fmaf(fv.z, w2[j], t);
            t = fmaf(fv.w, w3[j], t);
            acc[j] = t;
        }
    }

#pragma unroll
    for (int j = 0; j < 36; j++) acc[j] += reg_b[j];
#pragma unroll
    for (int a = 0; a < 9; a++) {
        const float z = acc[36 + a] + cls_b[a];
        acc[36 + a] = 1.0f / (1.0f + expf(-z));
    }

    float* o = out + (size_t)p * 45;
#pragma unroll
    for (int a = 0; a < 9; a++) {
        const bool keep = (acc[36 + a] > 0.7f) &&
                          (acc[4 * a + 2] > 10.0f) &&
                          (acc[4 * a + 3] > 10.0f);
        const float m = keep ? 1.0f : 0.0f;
        o[4 * a + 0] = acc[4 * a + 0] * m;
        o[4 * a + 1] = acc[4 * a + 1] * m;
        o[4 * a + 2] = acc[4 * a + 2] * m;
        o[4 * a + 3] = acc[4 * a + 3] * m;
        o[36 + a]    = acc[36 + a];
    }
}

extern "C" void kernel_launch(void* const* d_in, const int* in_sizes, int n_in,
                              void* d_out, int out_size)
{
    const float* x      = (const float*)d_in[0];
    const float* base_w = (const float*)d_in[1];
    const float* base_b = (const float*)d_in[2];
    const float* cls_w  = (const float*)d_in[3];
    const float* cls_b  = (const float*)d_in[4];
    const float* reg_w  = (const float*)d_in[5];
    const float* reg_b  = (const float*)d_in[6];
    float* out = (float*)d_out;

    dim3 g1(2, 1024, 1);
    conv3x3_relu_kernel<<<g1, 256>>>(x, base_w, base_b);
    rpn_head_kernel<<<512, 256>>>(cls_w, cls_b, reg_w, reg_b, out);
}

// round 7
// speedup vs baseline: 1.0566x; 1.0009x over previous
#include <cuda_runtime.h>
#include <math.h>

// Shapes:
//   x      [32,64,64,512] f32 NHWC
//   base_w [3,3,512,256]  HWIO
//   base_b [256]
//   cls_w  [1,1,256,9], cls_b [9]
//   reg_w  [1,1,256,36], reg_b [36]
//   out    [32,64,64,45]

#define NPIX (32 * 64 * 64)

__device__ float g_feat[(size_t)NPIX * 256];

// ---- packed f32x2 helpers (Blackwell FFMA2 path; ptxas won't auto-fuse) ----
__device__ __forceinline__ void fma2(unsigned long long& d,
                                     unsigned long long a,
                                     unsigned long long b)
{
    asm("fma.rn.f32x2 %0, %1, %2, %0;" : "+l"(d) : "l"(a), "l"(b));
}
__device__ __forceinline__ unsigned long long dup2(float v)
{
    unsigned long long r;
    unsigned u = __float_as_uint(v);
    asm("mov.b64 %0, {%1, %1};" : "=l"(r) : "r"(u));
    return r;
}

// ---------------------------------------------------------------------------
// Stage 1: 3x3 conv + bias + ReLU, implicit GEMM.
//   M = NPIX, N = 256, K = 9*512. BM=128, BN=128, BK=8, 256 thr, 8x8/thread.
//   Double-buffered SMEM (1 bar/k-tile) + packed FFMA2 inner product.
// ---------------------------------------------------------------------------
__global__ void __launch_bounds__(256, 2)
conv3x3_relu_kernel(const float* __restrict__ x,
                    const float* __restrict__ wbase,
                    const float* __restrict__ bbase)
{
    __shared__ float As[2][8][132];   // transposed [k][m], pad 132 (conflict-free)
    __shared__ float Bs[2][8][128];

    const int tid  = threadIdx.x;
    const int nblk = blockIdx.x;      // 0..1
    const int mblk = blockIdx.y;      // 0..1023

    // global-load mapping
    const int arow = tid >> 1;        // 0..127 pixel
    const int acol = tid & 1;         // k-quad
    const int brow = tid >> 5;        // 0..7 k row
    const int bcol = tid & 31;        // n-quad

    const int p  = mblk * 128 + arow;
    const int pb = p >> 12;
    const int ph = (p >> 6) & 63;
    const int pw = p & 63;

    // compute mapping: 16x16 threads, 8x8 outputs
    const int tr = tid >> 4;
    const int tc = tid & 15;
    const int m0 = tr * 8;
    const int n0 = tc * 8;

    // packed accumulators: acc2[i][j2] = {acc[i][2j2], acc[i][2j2+1]}
    unsigned long long acc2[8][4];
#pragma unroll
    for (int i = 0; i < 8; i++)
#pragma unroll
        for (int j = 0; j < 4; j++) acc2[i][j] = 0ull;

    int buf = 0;

#pragma unroll 1
    for (int pos = 0; pos < 9; pos++) {
        const int ky  = pos / 3;
        const int kx  = pos - ky * 3;
        const int hin = ph + ky - 1;
        const int win = pw + kx - 1;
        const bool valid = ((unsigned)hin < 64u) && ((unsigned)win < 64u);
        const float* aptr = x + ((((pb * 64 + hin) * 64) + win) * 512 + acol * 4);
        const float* bptr = wbase + (pos * 512 * 256 + brow * 256 + nblk * 128 + bcol * 4);

        // prologue: stage cc=0 into the idle buffer
        {
            float4 av = make_float4(0.f, 0.f, 0.f, 0.f);
            if (valid) av = *(const float4*)(aptr);
            const float4 bv = *(const float4*)(bptr);
            const int nb = buf ^ 1;
            As[nb][acol * 4 + 0][arow] = av.x;
            As[nb][acol * 4 + 1][arow] = av.y;
            As[nb][acol * 4 + 2][arow] = av.z;
            As[nb][acol * 4 + 3][arow] = av.w;
            *(float4*)(&Bs[nb][brow][bcol * 4]) = bv;
            __syncthreads();
            buf = nb;
        }

#pragma unroll 1
        for (int cc = 0; cc < 64; cc++) {
            float4 av2, bv2;
            if (cc < 63) {
                av2 = make_float4(0.f, 0.f, 0.f, 0.f);
                if (valid) av2 = *(const float4*)(aptr + (cc + 1) * 8);
                bv2 = *(const float4*)(bptr + (cc + 1) * 2048);
            }

#pragma unroll
            for (int k = 0; k < 8; k++) {
                const float* asrc = &As[buf][k][m0];
                const float4 a0 = *(const float4*)(asrc);
                const float4 a1 = *(const float4*)(asrc + 4);
                const unsigned long long* bp =
                    (const unsigned long long*)(&Bs[buf][k][n0]);
                const unsigned long long b0 = bp[0], b1 = bp[1],
                                         b2 = bp[2], b3 = bp[3];

                unsigned long long ad;
                ad = dup2(a0.x);
                fma2(acc2[0][0], ad, b0); fma2(acc2[0][1], ad, b1);
                fma2(acc2[0][2], ad, b2); fma2(acc2[0][3], ad, b3);
                ad = dup2(a0.y);
                fma2(acc2[1][0], ad, b0); fma2(acc2[1][1], ad, b1);
                fma2(acc2[1][2], ad, b2); fma2(acc2[1][3], ad, b3);
                ad = dup2(a0.z);
                fma2(acc2[2][0], ad, b0); fma2(acc2[2][1], ad, b1);
                fma2(acc2[2][2], ad, b2); fma2(acc2[2][3], ad, b3);
                ad = dup2(a0.w);
                fma2(acc2[3][0], ad, b0); fma2(acc2[3][1], ad, b1);
                fma2(acc2[3][2], ad, b2); fma2(acc2[3][3], ad, b3);
                ad = dup2(a1.x);
                fma2(acc2[4][0], ad, b0); fma2(acc2[4][1], ad, b1);
                fma2(acc2[4][2], ad, b2); fma2(acc2[4][3], ad, b3);
                ad = dup2(a1.y);
                fma2(acc2[5][0], ad, b0); fma2(acc2[5][1], ad, b1);
                fma2(acc2[5][2], ad, b2); fma2(acc2[5][3], ad, b3);
                ad = dup2(a1.z);
                fma2(acc2[6][0], ad, b0); fma2(acc2[6][1], ad, b1);
                fma2(acc2[6][2], ad, b2); fma2(acc2[6][3], ad, b3);
                ad = dup2(a1.w);
                fma2(acc2[7][0], ad, b0); fma2(acc2[7][1], ad, b1);
                fma2(acc2[7][2], ad, b2); fma2(acc2[7][3], ad, b3);
            }

            if (cc < 63) {
                const int nb = buf ^ 1;
                As[nb][acol * 4 + 0][arow] = av2.x;
                As[nb][acol * 4 + 1][arow] = av2.y;
                As[nb][acol * 4 + 2][arow] = av2.z;
                As[nb][acol * 4 + 3][arow] = av2.w;
                *(float4*)(&Bs[nb][brow][bcol * 4]) = bv2;
                __syncthreads();
                buf = nb;
            }
        }
    }

    // epilogue: bias + ReLU, store feat tile
    float bias[8];
#pragma unroll
    for (int j = 0; j < 8; j++) bias[j] = bbase[nblk * 128 + n0 + j];

#pragma unroll
    for (int i = 0; i < 8; i++) {
        const int pm = mblk * 128 + m0 + i;
        float* dst = g_feat + (size_t)pm * 256 + nblk * 128 + n0;
        float v[8];
#pragma unroll
        for (int j2 = 0; j2 < 4; j2++) {
            v[2 * j2 + 0] = __uint_as_float((unsigned)(acc2[i][j2] & 0xffffffffull));
            v[2 * j2 + 1] = __uint_as_float((unsigned)(acc2[i][j2] >> 32));
        }
        float4 v0, v1;
        v0.x = fmaxf(v[0] + bias[0], 0.f);
        v0.y = fmaxf(v[1] + bias[1], 0.f);
        v0.z = fmaxf(v[2] + bias[2], 0.f);
        v0.w = fmaxf(v[3] + bias[3], 0.f);
        v1.x = fmaxf(v[4] + bias[4], 0.f);
        v1.y = fmaxf(v[5] + bias[5], 0.f);
        v1.z = fmaxf(v[6] + bias[6], 0.f);
        v1.w = fmaxf(v[7] + bias[7], 0.f);
        *(float4*)(dst)     = v0;
        *(float4*)(dst + 4) = v1;
    }
}

// ---------------------------------------------------------------------------
// Stage 2: fused 1x1 heads + sigmoid + anchor filter + concat store.
// ---------------------------------------------------------------------------
__global__ void __launch_bounds__(256)
rpn_head_kernel(const float* __restrict__ cls_w,
                const float* __restrict__ cls_b,
                const float* __restrict__ reg_w,
                const float* __restrict__ reg_b,
                float* __restrict__ out)
{
    __shared__ float wsm[256 * 45];
    for (int idx = threadIdx.x; idx < 256 * 45; idx += 256) {
        const int c = idx / 45;
        const int j = idx - c * 45;
        wsm[idx] = (j < 36) ? reg_w[c * 36 + j] : cls_w[c * 9 + (j - 36)];
    }
    __syncthreads();

    const int p = blockIdx.x * 256 + threadIdx.x;
    const float* f = g_feat + (size_t)p * 256;

    float acc[45];
#pragma unroll
    for (int j = 0; j < 45; j++) acc[j] = 0.0f;

#pragma unroll 1
    for (int c4 = 0; c4 < 64; c4++) {
        const float4 fv = *(const float4*)(f + c4 * 4);
        const float* w0 = &wsm[(c4 * 4 + 0) * 45];
        const float* w1 = &wsm[(c4 * 4 + 1) * 45];
        const float* w2 = &wsm[(c4 * 4 + 2) * 45];
        const float* w3 = &wsm[(c4 * 4 + 3) * 45];
#pragma unroll
        for (int j = 0; j < 45; j++) {
            float t = acc[j];
            t = fmaf(fv.x, w0[j], t);
            t = fmaf(fv.y, w1[j], t);
            t = fmaf(fv.z, w2[j], t);
            t = fmaf(fv.w, w3[j], t);
            acc[j] = t;
        }
    }

#pragma unroll
    for (int j = 0; j < 36; j++) acc[j] += reg_b[j];
#pragma unroll
    for (int a = 0; a < 9; a++) {
        const float z = acc[36 + a] + cls_b[a];
        acc[36 + a] = 1.0f / (1.0f + expf(-z));
    }

    float* o = out + (size_t)p * 45;
#pragma unroll
    for (int a = 0; a < 9; a++) {
        const bool keep = (acc[36 + a] > 0.7f) &&
                          (acc[4 * a + 2] > 10.0f) &&
                          (acc[4 * a + 3] > 10.0f);
        const float m = keep ? 1.0f : 0.0f;
        o[4 * a + 0] = acc[4 * a + 0] * m;
        o[4 * a + 1] = acc[4 * a + 1] * m;
        o[4 * a + 2] = acc[4 * a + 2] * m;
        o[4 * a + 3] = acc[4 * a + 3] * m;
        o[36 + a]    = acc[36 + a];
    }
}

extern "C" void kernel_launch(void* const* d_in, const int* in_sizes, int n_in,
                              void* d_out, int out_size)
{
    const float* x      = (const float*)d_in[0];
    const float* base_w = (const float*)d_in[1];
    const float* base_b = (const float*)d_in[2];
    const float* cls_w  = (const float*)d_in[3];
    const float* cls_b  = (const float*)d_in[4];
    const float* reg_w  = (const float*)d_in[5];
    const float* reg_b  = (const float*)d_in[6];
    float* out = (float*)d_out;

    dim3 g1(2, 1024, 1);
    conv3x3_relu_kernel<<<g1, 256>>>(x, base_w, base_b);
    rpn_head_kernel<<<512, 256>>>(cls_w, cls_b, reg_w, reg_b, out);
}